// round 5
// baseline (speedup 1.0000x reference)
#include <cuda_runtime.h>
#include <cstdint>
#include <cstddef>

#define Bb 32
#define Dd 256
#define Ll 4096
#define Kk 1024
#define Nn (Bb*Ll)            // 131072 rows
#define NDL (Bb*Dd*Ll)        // 33554432 z_q elements
#define TL 32                 // l-tile for gather
#define RESC_CAP 16384
#define TAU 1e-4f

__device__ int    g_idx[Nn];
__device__ float  g_enorm[Kk];
__device__ double g_acc;
__device__ float  g_bh[Kk * Dd];   // emb tf32-high
__device__ float  g_bl[Kk * Dd];   // emb tf32-low
__device__ int    g_resc_cnt;
__device__ int    g_resc[RESC_CAP];

// ---------------------------------------------------------------------------
// helpers
// ---------------------------------------------------------------------------
__device__ __forceinline__ uint32_t smem_u32(const void* p) {
    uint32_t a;
    asm("{ .reg .u64 t; cvta.to.shared.u64 t, %1; cvt.u32.u64 %0, t; }"
        : "=r"(a) : "l"(p));
    return a;
}
__device__ __forceinline__ uint32_t tf32bits(float x) {
    uint32_t r; asm("cvt.rna.tf32.f32 %0, %1;" : "=r"(r) : "f"(x)); return r;
}
__device__ __forceinline__ float tf32f(float x) {
    return __uint_as_float(tf32bits(x));
}
__device__ __forceinline__ void cp16(uint32_t dst, const void* src) {
    asm volatile("cp.async.cg.shared.global [%0], [%1], 16;"
                 :: "r"(dst), "l"(src) : "memory");
}
#define CP_COMMIT() asm volatile("cp.async.commit_group;" ::: "memory")
#define CP_WAIT0()  asm volatile("cp.async.wait_group 0;" ::: "memory")

__device__ __forceinline__ void mma8(float* c, const uint32_t* a,
                                     uint32_t b0, uint32_t b1) {
    asm volatile("mma.sync.aligned.m16n8k8.row.col.f32.tf32.tf32.f32 "
        "{%0,%1,%2,%3}, {%4,%5,%6,%7}, {%8,%9}, {%0,%1,%2,%3};"
        : "+f"(c[0]), "+f"(c[1]), "+f"(c[2]), "+f"(c[3])
        : "r"(a[0]), "r"(a[1]), "r"(a[2]), "r"(a[3]), "r"(b0), "r"(b1));
}

// ---------------------------------------------------------------------------
// smem layout (bytes)
// ---------------------------------------------------------------------------
#define AS_STRIDE 260
#define BS_STRIDE 36
#define SM_AS   0
#define SM_B    133120
#define B_BUF   36864                  // bytes per (Bh+Bl) stage
#define B_HL    18432                  // bytes per single tile (128*36*4)
#define SM_EN   (SM_B + 2*B_BUF)       // 206848
#define SM_ZN   (SM_EN + 4096)         // 210944
#define SM_TOTAL (SM_ZN + 512)         // 211456

// ---------------------------------------------------------------------------
// prep: per-code squared norms + zero accumulators
// ---------------------------------------------------------------------------
__global__ void vq_prep_kernel(const float* __restrict__ emb) {
    int k = blockIdx.x * blockDim.x + threadIdx.x;
    if (k == 0) { g_acc = 0.0; g_resc_cnt = 0; }
    if (k < Kk) {
        const float* row = emb + (size_t)k * Dd;
        float s = 0.f;
        #pragma unroll 8
        for (int d = 0; d < Dd; d++) { float v = row[d]; s += v * v; }
        g_enorm[k] = s;
    }
}

// split emb into tf32 high/low parts (once per launch, reused by 1024 CTAs)
__global__ void vq_split_kernel(const float* __restrict__ emb) {
    int i = blockIdx.x * blockDim.x + threadIdx.x;
    if (i < Kk * Dd) {
        float v = emb[i];
        float h = tf32f(v);
        g_bh[i] = h;
        g_bl[i] = tf32f(v - h);
    }
}

// ---------------------------------------------------------------------------
// scores stage 1: tf32x3 mma.sync GEMM (128 rows x 1024 codes per CTA)
// + fused argmin with second-best tracking; near-ties go to rescue list
// ---------------------------------------------------------------------------
__global__ void __launch_bounds__(256, 1)
vq_scores_kernel(const float* __restrict__ z) {
    extern __shared__ char smem[];
    const uint32_t sb = smem_u32(smem);
    float*    As   = (float*)(smem + SM_AS);
    float*    s_en = (float*)(smem + SM_EN);
    float*    s_zn = (float*)(smem + SM_ZN);

    const int tid   = threadIdx.x;
    const int wid   = tid >> 5;
    const int lane  = tid & 31;
    const int g     = lane >> 2;       // groupID
    const int tig   = lane & 3;        // thread-in-group
    const int warpM = wid & 3;
    const int warpN = wid >> 2;
    const int m0    = warpM * 32;
    const int n0w   = warpN * 64;

    const int row0 = blockIdx.x * 128;
    const int b    = row0 >> 12;
    const int l0   = row0 & (Ll - 1);
    const float* zb = z + (size_t)b * Dd * Ll + l0;

    // stage z tile fp32: As[l][d], coalesced LDG
    for (int i = tid; i < 128 * Dd; i += 256) {
        int d = i >> 7, l = i & 127;
        As[l * AS_STRIDE + d] = zb[(size_t)d * Ll + l];
    }
    for (int i = tid; i < Kk; i += 256) s_en[i] = g_enorm[i];
    if (tid < 128) {
        float s = 0.f;
        #pragma unroll 8
        for (int d = 0; d < Dd; d++) { float v = zb[(size_t)d * Ll + tid]; s += v * v; }
        s_zn[tid] = s;
    }
    __syncthreads();

    // per-thread cp.async target offsets (4 float4 per tile)
    int cn[4], cj[4];
    uint32_t cso[4];
    #pragma unroll
    for (int q = 0; q < 4; q++) {
        int f4i = q * 256 + tid;
        cn[q]  = f4i >> 3;
        cj[q]  = (f4i & 7) * 4;
        cso[q] = (uint32_t)(cn[q] * BS_STRIDE + cj[q]) * 4u;
    }

    float zn_t[4];
    #pragma unroll
    for (int s = 0; s < 4; s++)
        zn_t[s] = s_zn[m0 + ((s >> 1) * 16) + ((s & 1) * 8) + g];

    float b1v[4], b2v[4];
    int   b1i[4];
    #pragma unroll
    for (int s = 0; s < 4; s++) { b1v[s] = 3.4e38f; b2v[s] = 3.4e38f; b1i[s] = 0; }

    #pragma unroll 1
    for (int nc = 0; nc < 8; nc++) {
        float acc[2][8][4];
        #pragma unroll
        for (int mt = 0; mt < 2; mt++)
            #pragma unroll
            for (int nt = 0; nt < 8; nt++)
                #pragma unroll
                for (int r = 0; r < 4; r++) acc[mt][nt][r] = 0.f;

        // prefetch d-chunk 0 into buffer 0
        #pragma unroll
        for (int q = 0; q < 4; q++) {
            size_t go = (size_t)(nc * 128 + cn[q]) * Dd + cj[q];
            cp16(sb + SM_B + cso[q],        g_bh + go);
            cp16(sb + SM_B + B_HL + cso[q], g_bl + go);
        }
        CP_COMMIT();

        #pragma unroll 1
        for (int dc = 0; dc < 8; dc++) {
            const int buf = dc & 1;
            CP_WAIT0();
            __syncthreads();
            if (dc < 7) {
                const uint32_t bdst = sb + SM_B + (uint32_t)((buf ^ 1) * B_BUF);
                #pragma unroll
                for (int q = 0; q < 4; q++) {
                    size_t go = (size_t)(nc * 128 + cn[q]) * Dd + (dc + 1) * 32 + cj[q];
                    cp16(bdst + cso[q],        g_bh + go);
                    cp16(bdst + B_HL + cso[q], g_bl + go);
                }
                CP_COMMIT();
            }

            const uint32_t* Bh = (const uint32_t*)(smem + SM_B + buf * B_BUF);
            const uint32_t* Bl = (const uint32_t*)(smem + SM_B + buf * B_BUF + B_HL);

            #pragma unroll
            for (int ks = 0; ks < 4; ks++) {
                const int dcol = dc * 32 + ks * 8 + tig;
                uint32_t ah[2][4], al[2][4];
                #pragma unroll
                for (int mt = 0; mt < 2; mt++) {
                    const float* ap = As + (m0 + mt * 16 + g) * AS_STRIDE + dcol;
                    float v0 = ap[0];
                    float v1 = ap[8 * AS_STRIDE];
                    float v2 = ap[4];
                    float v3 = ap[8 * AS_STRIDE + 4];
                    ah[mt][0] = tf32bits(v0); al[mt][0] = tf32bits(v0 - __uint_as_float(ah[mt][0]));
                    ah[mt][1] = tf32bits(v1); al[mt][1] = tf32bits(v1 - __uint_as_float(ah[mt][1]));
                    ah[mt][2] = tf32bits(v2); al[mt][2] = tf32bits(v2 - __uint_as_float(ah[mt][2]));
                    ah[mt][3] = tf32bits(v3); al[mt][3] = tf32bits(v3 - __uint_as_float(ah[mt][3]));
                }
                #pragma unroll
                for (int nt = 0; nt < 8; nt++) {
                    const int n = n0w + nt * 8 + g;
                    const int bo = n * BS_STRIDE + ks * 8 + tig;
                    uint32_t bh0 = Bh[bo], bh1 = Bh[bo + 4];
                    uint32_t bl0 = Bl[bo], bl1 = Bl[bo + 4];
                    #pragma unroll
                    for (int mt = 0; mt < 2; mt++) {
                        // per-chunk zero-init: bound RZ-accumulator drift
                        float c[4] = {0.f, 0.f, 0.f, 0.f};
                        mma8(c, ah[mt], bh0, bh1);   // zh.eh
                        mma8(c, ah[mt], bl0, bl1);   // zh.el
                        mma8(c, al[mt], bh0, bh1);   // zl.eh
                        acc[mt][nt][0] += c[0];
                        acc[mt][nt][1] += c[1];
                        acc[mt][nt][2] += c[2];
                        acc[mt][nt][3] += c[3];
                    }
                }
            }
        }
        __syncthreads();   // mma LDS done before next nc's cp.async overwrites

        // epilogue: dist + best/second-best, ascending k per slot
        #pragma unroll
        for (int nt = 0; nt < 8; nt++) {
            const int kb = nc * 128 + n0w + nt * 8 + 2 * tig;
            const float e0 = s_en[kb], e1 = s_en[kb + 1];
            #pragma unroll
            for (int mt = 0; mt < 2; mt++) {
                const int s0 = 2 * mt, s1 = 2 * mt + 1;
                float d0 = (zn_t[s0] + e0) - 2.f * acc[mt][nt][0];
                float d1 = (zn_t[s0] + e1) - 2.f * acc[mt][nt][1];
                float d2 = (zn_t[s1] + e0) - 2.f * acc[mt][nt][2];
                float d3 = (zn_t[s1] + e1) - 2.f * acc[mt][nt][3];
                if (d0 < b1v[s0]) { b2v[s0] = b1v[s0]; b1v[s0] = d0; b1i[s0] = kb; }
                else if (d0 < b2v[s0]) b2v[s0] = d0;
                if (d1 < b1v[s0]) { b2v[s0] = b1v[s0]; b1v[s0] = d1; b1i[s0] = kb + 1; }
                else if (d1 < b2v[s0]) b2v[s0] = d1;
                if (d2 < b1v[s1]) { b2v[s1] = b1v[s1]; b1v[s1] = d2; b1i[s1] = kb; }
                else if (d2 < b2v[s1]) b2v[s1] = d2;
                if (d3 < b1v[s1]) { b2v[s1] = b1v[s1]; b1v[s1] = d3; b1i[s1] = kb + 1; }
                else if (d3 < b2v[s1]) b2v[s1] = d3;
            }
        }
    }

    // reduce across tig quad (same rows), tracking best + second-best
    #pragma unroll
    for (int s = 0; s < 4; s++) {
        #pragma unroll
        for (int off = 1; off <= 2; off <<= 1) {
            float o1v = __shfl_xor_sync(0xffffffffu, b1v[s], off);
            int   o1i = __shfl_xor_sync(0xffffffffu, b1i[s], off);
            float o2v = __shfl_xor_sync(0xffffffffu, b2v[s], off);
            if (o1v < b1v[s] || (o1v == b1v[s] && o1i < b1i[s])) {
                b2v[s] = fminf(b1v[s], o2v);
                b1v[s] = o1v; b1i[s] = o1i;
            } else {
                b2v[s] = fminf(o1v, b2v[s]);
            }
        }
    }

    // merge the two warpN halves via smem (reuse B buffer region)
    float* mv  = (float*)(smem + SM_B);
    int*   mi  = (int*)(smem + SM_B + 512);
    float* mv2 = (float*)(smem + SM_B + 1024);
    __syncthreads();
    if (warpN == 1 && tig == 0) {
        #pragma unroll
        for (int s = 0; s < 4; s++) {
            int row = m0 + (s >> 1) * 16 + (s & 1) * 8 + g;
            mv[row] = b1v[s]; mi[row] = b1i[s]; mv2[row] = b2v[s];
        }
    }
    __syncthreads();
    if (warpN == 0 && tig == 0) {
        #pragma unroll
        for (int s = 0; s < 4; s++) {
            int row = m0 + (s >> 1) * 16 + (s & 1) * 8 + g;
            float o1v = mv[row]; int o1i = mi[row]; float o2v = mv2[row];
            float v1 = b1v[s]; int i1 = b1i[s]; float v2 = b2v[s];
            if (o1v < v1 || (o1v == v1 && o1i < i1)) {
                v2 = fminf(v1, o2v); v1 = o1v; i1 = o1i;
            } else {
                v2 = fminf(o1v, v2);
            }
            g_idx[row0 + row] = i1;
            if (v2 - v1 < TAU) {
                int p = atomicAdd(&g_resc_cnt, 1);
                if (p < RESC_CAP) g_resc[p] = row0 + row;
            }
        }
    }
}

// ---------------------------------------------------------------------------
// rescue: exact sequential-fp32 recompute for near-tie rows (matches the
// reference's accumulation structure; same arithmetic that passed in R1)
// ---------------------------------------------------------------------------
__global__ void __launch_bounds__(128)
vq_rescue_kernel(const float* __restrict__ z, const float* __restrict__ emb) {
    __shared__ float zrow[Dd];
    __shared__ float sv[128];
    __shared__ int   si[128];

    int cnt = g_resc_cnt;
    if (cnt > RESC_CAP) cnt = RESC_CAP;
    if ((int)blockIdx.x >= cnt) return;

    const int tid = threadIdx.x;
    const int row = g_resc[blockIdx.x];
    const int b   = row >> 12;
    const int l   = row & (Ll - 1);
    const float* zb = z + (size_t)b * Dd * Ll + l;

    for (int d = tid; d < Dd; d += 128) zrow[d] = zb[(size_t)d * Ll];
    __syncthreads();

    // sequential fp32 ||z||^2 (redundant per thread; identical result)
    float zn = 0.f;
    #pragma unroll 8
    for (int d = 0; d < Dd; d++) { float v = zrow[d]; zn += v * v; }

    float bv = 3.4e38f;
    int   bi = 0;
    for (int k = tid; k < Kk; k += 128) {      // ascending k per thread
        const float* e = emb + (size_t)k * Dd;
        float acc = 0.f;
        #pragma unroll 8
        for (int d = 0; d < Dd; d++) acc = fmaf(zrow[d], e[d], acc);
        float dist = (zn + g_enorm[k]) - 2.0f * acc;
        if (dist < bv) { bv = dist; bi = k; }
    }

    sv[tid] = bv; si[tid] = bi;
    __syncthreads();
    for (int off = 64; off; off >>= 1) {
        if (tid < off) {
            float ov = sv[tid + off]; int oi = si[tid + off];
            if (ov < sv[tid] || (ov == sv[tid] && oi < si[tid])) {
                sv[tid] = ov; si[tid] = oi;
            }
        }
        __syncthreads();
    }
    if (tid == 0) g_idx[row] = si[0];
}

// ---------------------------------------------------------------------------
// gather: z_q_st = embedding[idx] scattered to (B,D,L); fused sum((z-q)^2)
// ---------------------------------------------------------------------------
__global__ void __launch_bounds__(256)
vq_gather_kernel(const float* __restrict__ z, const float* __restrict__ emb,
                 float* __restrict__ out) {
    __shared__ float q[TL][Dd + 1];
    __shared__ int   idxs[TL];
    __shared__ float wsum[8];

    const int tid = threadIdx.x;
    const int t   = blockIdx.x;
    const int b   = t >> 7;
    const int l0  = (t & 127) * TL;
    const int rbase = b * Ll + l0;

    if (tid < TL) idxs[tid] = g_idx[rbase + tid];
    __syncthreads();

    for (int i = tid; i < TL * Dd; i += 256) {
        int r = i >> 8, d = i & 255;
        q[r][d] = emb[(size_t)idxs[r] * Dd + d];
    }
    __syncthreads();

    float lsum = 0.f;
    const float* zb = z   + (size_t)b * Dd * Ll + l0;
    float*       ob = out + (size_t)b * Dd * Ll + l0;
    for (int i = tid; i < Dd * TL; i += 256) {
        int d = i >> 5, lr = i & 31;
        float v  = q[lr][d];
        float ze = zb[(size_t)d * Ll + lr];
        ob[(size_t)d * Ll + lr] = v;
        float df = ze - v;
        lsum += df * df;
    }

    #pragma unroll
    for (int off = 16; off; off >>= 1)
        lsum += __shfl_xor_sync(0xffffffffu, lsum, off);
    if ((tid & 31) == 0) wsum[tid >> 5] = lsum;
    __syncthreads();
    if (tid == 0) {
        float s = 0.f;
        #pragma unroll
        for (int w = 0; w < 8; w++) s += wsum[w];
        atomicAdd(&g_acc, (double)s);
    }
}

// ---------------------------------------------------------------------------
__global__ void vq_tail_kernel(float* __restrict__ out) {
    int i = blockIdx.x * blockDim.x + threadIdx.x;
    if (i < Nn) out[NDL + i] = (float)g_idx[i];
}

__global__ void vq_loss_kernel(float* __restrict__ out) {
    double mse = g_acc / (double)NDL;
    out[NDL + Nn + 0] = (float)(1.25 * mse);
    out[NDL + Nn + 1] = (float)mse;
    out[NDL + Nn + 2] = (float)(0.25 * mse);
}

// ---------------------------------------------------------------------------
extern "C" void kernel_launch(void* const* d_in, const int* in_sizes, int n_in,
                              void* d_out, int out_size) {
    const float* z   = (const float*)d_in[0];
    const float* emb = (const float*)d_in[1];
    if (n_in >= 2 && in_sizes[0] == Kk * Dd && in_sizes[1] == NDL) {
        emb = (const float*)d_in[0];
        z   = (const float*)d_in[1];
    }
    float* out = (float*)d_out;

    cudaFuncSetAttribute(vq_scores_kernel,
                         cudaFuncAttributeMaxDynamicSharedMemorySize, SM_TOTAL);

    vq_prep_kernel<<<(Kk + 255) / 256, 256>>>(emb);
    vq_split_kernel<<<(Kk * Dd + 255) / 256, 256>>>(emb);
    vq_scores_kernel<<<Nn / 128, 256, SM_TOTAL>>>(z);
    vq_rescue_kernel<<<RESC_CAP, 128>>>(z, emb);
    vq_gather_kernel<<<Nn / TL, 256>>>(z, emb, out);
    if (out_size >= NDL + Nn)
        vq_tail_kernel<<<(Nn + 255) / 256, 256>>>(out);
    if (out_size >= NDL + Nn + 3)
        vq_loss_kernel<<<1, 1>>>(out);
}